// round 1
// baseline (speedup 1.0000x reference)
#include <cuda_runtime.h>
#include <math.h>

// Problem constants (fixed by the dataset)
#define NU 60000
#define NI 40000
#define NN 100000     // NU + NI
#define NE 500000
#define D  64
#define K  4
// dk = 16, 8 lanes * float2 per factor

// ---------------- static device scratch (no runtime allocation) ----------------
__device__ float g_ego0[NN * D];
__device__ float g_ego1[NN * D];
__device__ float g_all [NN * D];
__device__ float g_tv  [NN * D];
__device__ float g_S   [K * NE];
__device__ float g_enorm[NE];
__device__ float g_dinv [NN];
__device__ float g_rn   [NN * K];
__device__ int   g_deg  [NN];

// ---------------- kernels ----------------

// ego = concat(user, item); all_embs = ego
__global__ void k_initego(const float* __restrict__ u, const float* __restrict__ it) {
    int i = blockIdx.x * blockDim.x + threadIdx.x;
    if (i >= NN * D) return;
    float v = (i < NU * D) ? u[i] : it[i - NU * D];
    g_ego0[i] = v;
    g_all[i]  = v;
}

// symmetric degree
__global__ void k_deg(const int* __restrict__ ei) {
    int j = blockIdx.x * blockDim.x + threadIdx.x;
    if (j >= NE) return;
    atomicAdd(&g_deg[ei[j]], 1);
    atomicAdd(&g_deg[ei[NE + j]], 1);
}

__global__ void k_dinv() {
    int n = blockIdx.x * blockDim.x + threadIdx.x;
    if (n >= NN) return;
    int d = g_deg[n];
    g_dinv[n] = (d > 0) ? (1.0f / sqrtf((float)d)) : 0.0f;
}

// per-edge symmetric norm: dinv[row]*dinv[col]
__global__ void k_enorm(const int* __restrict__ ei) {
    int j = blockIdx.x * blockDim.x + threadIdx.x;
    if (j >= NE) return;
    g_enorm[j] = g_dinv[ei[j]] * g_dinv[ei[NE + j]];
}

// softmax over the 4 factors, per edge, in place
__global__ void k_softmax() {
    int j = blockIdx.x * blockDim.x + threadIdx.x;
    if (j >= NE) return;
    float s0 = g_S[j], s1 = g_S[NE + j], s2 = g_S[2 * NE + j], s3 = g_S[3 * NE + j];
    float m  = fmaxf(fmaxf(s0, s1), fmaxf(s2, s3));
    float e0 = expf(s0 - m), e1 = expf(s1 - m), e2 = expf(s2 - m), e3 = expf(s3 - m);
    float r  = 1.0f / (e0 + e1 + e2 + e3);
    g_S[j] = e0 * r; g_S[NE + j] = e1 * r; g_S[2 * NE + j] = e2 * r; g_S[3 * NE + j] = e3 * r;
}

// conv: one warp per edge. lanes 0-15: out[col] += w*ego[row]; lanes 16-31: out[row] += w*ego[col]
__global__ void k_conv(const float* __restrict__ ego, float* __restrict__ xn,
                       const int* __restrict__ ei) {
    int gw = (blockIdx.x * blockDim.x + threadIdx.x) >> 5;
    if (gw >= NE) return;
    int lane = threadIdx.x & 31;
    int r = ei[gw];
    int c = ei[NE + gw];
    int half = lane >> 4;   // 0 = forward, 1 = reverse
    int q    = lane & 15;   // float4 index within the 64-float row
    int k    = q >> 2;      // factor (4 float4 = 16 floats per factor)
    float w  = g_enorm[gw] * g_S[k * NE + gw];

    int src = half ? c : r;
    int dst = half ? r : c;
    float4 v = reinterpret_cast<const float4*>(ego + (size_t)src * D)[q];
    float4* dp = reinterpret_cast<float4*>(xn + (size_t)dst * D) + q;
    asm volatile("red.global.add.v4.f32 [%0], {%1, %2, %3, %4};"
                 :: "l"(dp), "f"(v.x * w), "f"(v.y * w), "f"(v.z * w), "f"(v.w * w)
                 : "memory");
}

// per-node per-factor inverse L2 norm of x_new
__global__ void k_rn(const float* __restrict__ xn) {
    int gw = (blockIdx.x * blockDim.x + threadIdx.x) >> 5;
    if (gw >= NN) return;
    int lane = threadIdx.x & 31;
    float2 a = reinterpret_cast<const float2*>(xn + (size_t)gw * D)[lane];
    float ss = a.x * a.x + a.y * a.y;
    ss += __shfl_xor_sync(0xFFFFFFFF, ss, 1);
    ss += __shfl_xor_sync(0xFFFFFFFF, ss, 2);
    ss += __shfl_xor_sync(0xFFFFFFFF, ss, 4);
    if ((lane & 7) == 0)
        g_rn[gw * K + (lane >> 3)] = 1.0f / fmaxf(sqrtf(ss), 1e-12f);
}

// tv[n] = tanh(l2norm_per_factor(ego[n])) -- precomputed once per layer
__global__ void k_tv(const float* __restrict__ ego) {
    int gw = (blockIdx.x * blockDim.x + threadIdx.x) >> 5;
    if (gw >= NN) return;
    int lane = threadIdx.x & 31;
    float2 a = reinterpret_cast<const float2*>(ego + (size_t)gw * D)[lane];
    float ss = a.x * a.x + a.y * a.y;
    ss += __shfl_xor_sync(0xFFFFFFFF, ss, 1);
    ss += __shfl_xor_sync(0xFFFFFFFF, ss, 2);
    ss += __shfl_xor_sync(0xFFFFFFFF, ss, 4);
    float rinv = 1.0f / fmaxf(sqrtf(ss), 1e-12f);
    float2 o;
    o.x = tanhf(a.x * rinv);
    o.y = tanhf(a.y * rinv);
    reinterpret_cast<float2*>(g_tv + (size_t)gw * D)[lane] = o;
}

// S[k,j] += rn[row,k] * dot(x_new[row, kblk], tv[col, kblk]); one warp per edge
__global__ void k_score(const float* __restrict__ xn, const int* __restrict__ ei) {
    int gw = (blockIdx.x * blockDim.x + threadIdx.x) >> 5;
    if (gw >= NE) return;
    int lane = threadIdx.x & 31;
    int r = ei[gw];
    int c = ei[NE + gw];
    float2 a = reinterpret_cast<const float2*>(xn   + (size_t)r * D)[lane];
    float2 b = reinterpret_cast<const float2*>(g_tv + (size_t)c * D)[lane];
    float p = a.x * b.x + a.y * b.y;
    p += __shfl_xor_sync(0xFFFFFFFF, p, 1);
    p += __shfl_xor_sync(0xFFFFFFFF, p, 2);
    p += __shfl_xor_sync(0xFFFFFFFF, p, 4);
    if ((lane & 7) == 0) {
        int k = lane >> 3;
        g_S[k * NE + gw] += p * g_rn[r * K + k];
    }
}

// all_embs += x_new
__global__ void k_accum(const float* __restrict__ xn) {
    int i = blockIdx.x * blockDim.x + threadIdx.x;
    if (i >= NN * D) return;
    g_all[i] += xn[i];
}

// ---------------- host orchestration ----------------

extern "C" void kernel_launch(void* const* d_in, const int* in_sizes, int n_in,
                              void* d_out, int out_size) {
    const float* user = (const float*)d_in[0];
    const float* item = (const float*)d_in[1];
    const float* Sin  = (const float*)d_in[2];
    const int*   ei   = (const int*)d_in[3];
    float* out = (float*)d_out;

    void *p_deg, *p_ego0, *p_ego1, *p_S, *p_all;
    cudaGetSymbolAddress(&p_deg,  g_deg);
    cudaGetSymbolAddress(&p_ego0, g_ego0);
    cudaGetSymbolAddress(&p_ego1, g_ego1);
    cudaGetSymbolAddress(&p_S,    g_S);
    cudaGetSymbolAddress(&p_all,  g_all);

    const int T = 256;
    const int gElem = (NN * D + T - 1) / T;   // element-wise over embeddings
    const int gNode = (NN + T - 1) / T;
    const int gEdge = (NE + T - 1) / T;
    const int gEdgeW = (NE * 32 + T - 1) / T; // warp per edge
    const int gNodeW = (NN * 32 + T - 1) / T; // warp per node

    // setup
    cudaMemsetAsync(p_deg, 0, NN * sizeof(int), 0);
    k_initego<<<gElem, T>>>(user, item);
    cudaMemcpyAsync(p_S, Sin, (size_t)K * NE * sizeof(float), cudaMemcpyDeviceToDevice, 0);
    k_deg<<<gEdge, T>>>(ei);
    k_dinv<<<gNode, T>>>();
    k_enorm<<<gEdge, T>>>(ei);

    float* ego = (float*)p_ego0;
    float* xn  = (float*)p_ego1;

    for (int layer = 0; layer < 2; layer++) {
        k_tv<<<gNodeW, T>>>(ego);
        for (int it = 0; it < 2; it++) {
            k_softmax<<<gEdge, T>>>();
            cudaMemsetAsync(xn, 0, (size_t)NN * D * sizeof(float), 0);
            k_conv<<<gEdgeW, T>>>(ego, xn, ei);
            k_rn<<<gNodeW, T>>>(xn);
            k_score<<<gEdgeW, T>>>(xn, ei);
        }
        k_accum<<<gElem, T>>>(xn);
        float* t = ego; ego = xn; xn = t;
    }

    // output: [user_all | item_all | S]
    cudaMemcpyAsync(out, p_all, (size_t)NN * D * sizeof(float), cudaMemcpyDeviceToDevice, 0);
    cudaMemcpyAsync(out + (size_t)NN * D, p_S, (size_t)K * NE * sizeof(float),
                    cudaMemcpyDeviceToDevice, 0);
}